// round 15
// baseline (speedup 1.0000x reference)
#include <cuda_runtime.h>
#include <cuda_bf16.h>
#include <math.h>
#include <stdint.h>

#define N_NODES 40000
#define FEAT    128
#define HID     128
#define EMB     64
#define N_EDGES 640000

// Scratch: device globals, referenced ONLY from device code (host passes flags).
__device__ __align__(16) float    g_y1[N_NODES * 256];  // [t1|r1] per node (fp32)
__device__ __align__(16) float    g_y2[N_NODES * 128];  // [t2|r2] per node (fp32)
__device__ __align__(16) uint32_t g_xhi[N_NODES * 64];  // x as bf16x2 pairs (hi)
__device__ __align__(16) uint32_t g_xlo[N_NODES * 64];  // x residual (lo)
__device__ __align__(16) uint32_t g_hhi[N_NODES * 64];  // h as bf16x2 pairs (hi)
__device__ __align__(16) uint32_t g_hlo[N_NODES * 64];  // h residual (lo)
__device__ __align__(16) int g_deg[N_NODES];
__device__ int g_rowptr[N_NODES + 1];
__device__ int g_woff[N_NODES];
__device__ int g_esrc[N_EDGES];

// ---------------------------------------------------------------------------
__device__ __forceinline__ void split2(float a, float b, uint32_t& h, uint32_t& l) {
    __nv_bfloat162 th, tl;
    th.x = __float2bfloat16_rn(a);
    th.y = __float2bfloat16_rn(b);
    tl.x = __float2bfloat16_rn(a - __bfloat162float(th.x));
    tl.y = __float2bfloat16_rn(b - __bfloat162float(th.y));
    h = reinterpret_cast<uint32_t&>(th);
    l = reinterpret_cast<uint32_t&>(tl);
}

__device__ __forceinline__ void mma_bf16(float d[4],
                                         uint32_t a0, uint32_t a1, uint32_t a2, uint32_t a3,
                                         uint32_t b0, uint32_t b1) {
    asm volatile(
        "mma.sync.aligned.m16n8k16.row.col.f32.bf16.bf16.f32 "
        "{%0,%1,%2,%3}, {%4,%5,%6,%7}, {%8,%9}, {%0,%1,%2,%3};\n"
        : "+f"(d[0]), "+f"(d[1]), "+f"(d[2]), "+f"(d[3])
        : "r"(a0), "r"(a1), "r"(a2), "r"(a3), "r"(b0), "r"(b1));
}

// ---------------------------------------------------------------------------
__global__ void k_dzero() {
    int i = blockIdx.x * blockDim.x + threadIdx.x;
    if (i < N_NODES) g_deg[i] = 0;
}

__global__ void k_hist(const int* __restrict__ dst) {
    int e = blockIdx.x * blockDim.x + threadIdx.x;
    if (e >= N_EDGES) return;
    int d = dst[e];
    if ((unsigned)d < N_NODES) atomicAdd(&g_deg[d], 1);
}

// single-block exclusive prefix scan of g_deg -> g_rowptr, g_woff
__global__ __launch_bounds__(1024) void k_scan() {
    __shared__ int ssum[1024];
    const int t = threadIdx.x;
    const int CH = 40;                       // 1024*40 >= 40000
    int base = t * CH;
    int deg[CH];
    #pragma unroll
    for (int q = 0; q < CH / 4; q++) {
        int idx = base + q * 4;
        int4 v = (idx + 3 < N_NODES) ? ((const int4*)g_deg)[idx >> 2]
                                     : make_int4(idx + 0 < N_NODES ? g_deg[idx + 0] : 0,
                                                 idx + 1 < N_NODES ? g_deg[idx + 1] : 0,
                                                 idx + 2 < N_NODES ? g_deg[idx + 2] : 0,
                                                 idx + 3 < N_NODES ? g_deg[idx + 3] : 0);
        deg[q * 4 + 0] = v.x; deg[q * 4 + 1] = v.y;
        deg[q * 4 + 2] = v.z; deg[q * 4 + 3] = v.w;
    }
    int tsum = 0;
    #pragma unroll
    for (int c = 0; c < CH; c++) tsum += deg[c];
    ssum[t] = tsum;
    __syncthreads();
    for (int off = 1; off < 1024; off <<= 1) {
        int v = (t >= off) ? ssum[t - off] : 0;
        __syncthreads();
        ssum[t] += v;
        __syncthreads();
    }
    int running = ssum[t] - tsum;            // exclusive prefix
    #pragma unroll
    for (int c = 0; c < CH; c++) {
        int idx = base + c;
        if (idx < N_NODES) {
            g_rowptr[idx] = running;
            g_woff[idx]   = running;
            running += deg[c];
        }
    }
    if (t == 1023) g_rowptr[N_NODES] = running;
}

__global__ void k_permute(const int* __restrict__ src, const int* __restrict__ dst) {
    int e = blockIdx.x * blockDim.x + threadIdx.x;
    if (e >= N_EDGES) return;
    int d = dst[e], s = src[e];
    if ((unsigned)d >= N_NODES || (unsigned)s >= N_NODES) return;
    int pos = atomicAdd(&g_woff[d], 1);
    g_esrc[pos] = s;
}

// ---------------------------------------------------------------------------
// split x into bf16 hi/lo pair arrays
__global__ void k_conv(const float4* __restrict__ x) {
    int i = blockIdx.x * blockDim.x + threadIdx.x;  // over N_NODES*32 float4s
    if (i >= N_NODES * 32) return;
    float4 v = x[i];
    uint32_t h0, l0, h1, l1;
    split2(v.x, v.y, h0, l0);
    split2(v.z, v.w, h1, l1);
    g_xhi[i * 2]     = h0;
    g_xhi[i * 2 + 1] = h1;
    g_xlo[i * 2]     = l0;
    g_xlo[i * 2 + 1] = l1;
}

// ---------------------------------------------------------------------------
// Tensor-core GEMM over tile range [tile0, tile1).
template<int N2>
__global__ __launch_bounds__(256)
void k_gemmtc(const float* __restrict__ Wl, const float* __restrict__ Wr,
              int use_gh, int y_sel, int tile0, int tile1) {
    constexpr int DOUT = N2 / 2;
    constexpr int WC   = N2 / 64;           // 4 (N2=256) or 2 (N2=128)
    constexpr int WR   = 8 / WC;            // 2 or 4
    constexpr int MBLK = 16 * WR;           // 32 or 64

    extern __shared__ uint32_t smu[];
    uint32_t* Bhi = smu;                    // N2*68
    uint32_t* Blo = Bhi + N2 * 68;
    uint32_t* Ahi = Blo + N2 * 68;          // MBLK*68
    uint32_t* Alo = Ahi + MBLK * 68;

    const uint32_t* xhi = use_gh ? g_hhi : g_xhi;
    const uint32_t* xlo = use_gh ? g_hlo : g_xlo;
    float* y = (y_sel == 1) ? g_y1 : g_y2;

    const int tid = threadIdx.x;

    for (int idx = tid; idx < DOUT * 64; idx += 256) {
        int j = idx >> 6, k2 = idx & 63;
        float2 wl = ((const float2*)Wl)[idx];
        float2 wr = ((const float2*)Wr)[idx];
        uint32_t h, l;
        split2(wl.x, wl.y, h, l);
        Bhi[j * 68 + k2] = h;  Blo[j * 68 + k2] = l;
        split2(wr.x, wr.y, h, l);
        Bhi[(DOUT + j) * 68 + k2] = h;  Blo[(DOUT + j) * 68 + k2] = l;
    }
    __syncthreads();

    const int w    = tid >> 5, lane = tid & 31;
    const int wrow = w % WR,   wcol = w / WR;
    const int mo   = wrow * 16, no  = wcol * 64;
    const int g    = lane >> 2, c   = lane & 3;
    const int ar0  = (mo + g) * 68, ar1 = (mo + g + 8) * 68;

    for (int tile = tile0 + blockIdx.x; tile < tile1; tile += gridDim.x) {
        int base = tile * MBLK;

        for (int idx = tid; idx < MBLK * 64; idx += 256) {
            int ln = idx >> 6, k2 = idx & 63;
            int node = base + ln;
            uint32_t vh = 0, vl = 0;
            if (node < N_NODES) {
                size_t gi = (size_t)node * 64 + k2;
                vh = xhi[gi];
                vl = xlo[gi];
            }
            Ahi[ln * 68 + k2] = vh;
            Alo[ln * 68 + k2] = vl;
        }
        __syncthreads();

        float d[8][4];
        #pragma unroll
        for (int nt = 0; nt < 8; nt++)
            #pragma unroll
            for (int q = 0; q < 4; q++) d[nt][q] = 0.f;

        #pragma unroll 2
        for (int ks = 0; ks < 8; ks++) {
            int kp = ks * 8 + c;
            uint32_t ah0 = Ahi[ar0 + kp],     ah1 = Ahi[ar1 + kp];
            uint32_t ah2 = Ahi[ar0 + kp + 4], ah3 = Ahi[ar1 + kp + 4];
            uint32_t al0 = Alo[ar0 + kp],     al1 = Alo[ar1 + kp];
            uint32_t al2 = Alo[ar0 + kp + 4], al3 = Alo[ar1 + kp + 4];
            #pragma unroll
            for (int nt = 0; nt < 8; nt++) {
                int nr = (no + nt * 8 + g) * 68 + kp;
                uint32_t bh0 = Bhi[nr], bh1 = Bhi[nr + 4];
                uint32_t bl0 = Blo[nr], bl1 = Blo[nr + 4];
                mma_bf16(d[nt], ah0, ah1, ah2, ah3, bh0, bh1);
                mma_bf16(d[nt], ah0, ah1, ah2, ah3, bl0, bl1);
                mma_bf16(d[nt], al0, al1, al2, al3, bh0, bh1);
            }
        }

        #pragma unroll
        for (int nt = 0; nt < 8; nt++) {
            int col = no + nt * 8 + 2 * c;
            int row = base + mo + g;
            if (row < N_NODES) {
                size_t r0 = (size_t)row;
                *(float2*)(y + r0 * N2 + col)       = make_float2(d[nt][0], d[nt][1]);
                if (row + 8 < N_NODES)
                    *(float2*)(y + (r0 + 8) * N2 + col) = make_float2(d[nt][2], d[nt][3]);
            }
        }
        __syncthreads();
    }
}

// ---------------------------------------------------------------------------
// layer-1 aggregate+epilogue over node range [n0, n1):
// h[n] = ELU( mean_j t1[src_j] + b1 + r1[n] ), written as bf16 hi/lo pairs.
__global__ void k_agg1(const float* __restrict__ b1, int n0, int n1) {
    int w    = n0 + ((blockIdx.x * blockDim.x + threadIdx.x) >> 5);
    int lane = threadIdx.x & 31;
    if (w >= n1) return;
    const float4* y4 = (const float4*)g_y1;   // row stride = 64 float4 ([t|r])
    int beg = g_rowptr[w], end = g_rowptr[w + 1];
    float4 acc = make_float4(0.f, 0.f, 0.f, 0.f);
    int i = beg;
    for (; i + 4 <= end; i += 4) {
        int s0 = g_esrc[i], s1 = g_esrc[i + 1], s2 = g_esrc[i + 2], s3 = g_esrc[i + 3];
        float4 v0 = y4[(size_t)s0 * 64 + lane];
        float4 v1 = y4[(size_t)s1 * 64 + lane];
        float4 v2 = y4[(size_t)s2 * 64 + lane];
        float4 v3 = y4[(size_t)s3 * 64 + lane];
        acc.x += v0.x + v1.x + v2.x + v3.x;
        acc.y += v0.y + v1.y + v2.y + v3.y;
        acc.z += v0.z + v1.z + v2.z + v3.z;
        acc.w += v0.w + v1.w + v2.w + v3.w;
    }
    for (; i < end; i++) {
        float4 v = y4[(size_t)g_esrc[i] * 64 + lane];
        acc.x += v.x; acc.y += v.y; acc.z += v.z; acc.w += v.w;
    }
    float rc = 1.0f / (float)max(end - beg, 1);
    float4 r = y4[(size_t)w * 64 + 32 + lane];
    float4 b = ((const float4*)b1)[lane];
    float4 o;
    o.x = acc.x * rc + b.x + r.x;
    o.y = acc.y * rc + b.y + r.y;
    o.z = acc.z * rc + b.z + r.z;
    o.w = acc.w * rc + b.w + r.w;
    o.x = (o.x > 0.f) ? o.x : expm1f(o.x);
    o.y = (o.y > 0.f) ? o.y : expm1f(o.y);
    o.z = (o.z > 0.f) ? o.z : expm1f(o.z);
    o.w = (o.w > 0.f) ? o.w : expm1f(o.w);
    uint32_t h0, l0, h1, l1;
    split2(o.x, o.y, h0, l0);
    split2(o.z, o.w, h1, l1);
    size_t pi = (size_t)w * 64 + lane * 2;
    g_hhi[pi]     = h0;  g_hhi[pi + 1] = h1;
    g_hlo[pi]     = l0;  g_hlo[pi + 1] = l1;
}

// ---------------------------------------------------------------------------
// layer-2 aggregate + bias + log_softmax
__global__ void k_agg2(const float* __restrict__ b2, float* __restrict__ out) {
    int w    = (blockIdx.x * blockDim.x + threadIdx.x) >> 5;
    int lane = threadIdx.x & 31;
    if (w >= N_NODES) return;
    const float2* y2 = (const float2*)g_y2;   // row stride = 64 float2 ([t|r])
    int beg = g_rowptr[w], end = g_rowptr[w + 1];
    float2 acc = make_float2(0.f, 0.f);
    int i = beg;
    for (; i + 4 <= end; i += 4) {
        int s0 = g_esrc[i], s1 = g_esrc[i + 1], s2 = g_esrc[i + 2], s3 = g_esrc[i + 3];
        float2 v0 = y2[(size_t)s0 * 64 + lane];
        float2 v1 = y2[(size_t)s1 * 64 + lane];
        float2 v2 = y2[(size_t)s2 * 64 + lane];
        float2 v3 = y2[(size_t)s3 * 64 + lane];
        acc.x += v0.x + v1.x + v2.x + v3.x;
        acc.y += v0.y + v1.y + v2.y + v3.y;
    }
    for (; i < end; i++) {
        float2 v = y2[(size_t)g_esrc[i] * 64 + lane];
        acc.x += v.x; acc.y += v.y;
    }
    float rc = 1.0f / (float)max(end - beg, 1);
    float2 r = y2[(size_t)w * 64 + 32 + lane];
    float2 b = ((const float2*)b2)[lane];
    float l0 = acc.x * rc + b.x + r.x;
    float l1 = acc.y * rc + b.y + r.y;
    float m = fmaxf(l0, l1);
    #pragma unroll
    for (int o = 16; o; o >>= 1) m = fmaxf(m, __shfl_xor_sync(0xFFFFFFFFu, m, o));
    float s = expf(l0 - m) + expf(l1 - m);
    #pragma unroll
    for (int o = 16; o; o >>= 1) s += __shfl_xor_sync(0xFFFFFFFFu, s, o);
    float lz = m + logf(s);
    ((float2*)out)[(size_t)w * 32 + lane] = make_float2(l0 - lz, l1 - lz);
}

// ---------------------------------------------------------------------------
extern "C" void kernel_launch(void* const* d_in, const int* in_sizes, int n_in,
                              void* d_out, int out_size) {
    const float* x   = (const float*)d_in[0];
    const int*   src = (const int*)d_in[1];            // edge_index row 0 (int32)
    const int*   dst = src + N_EDGES;                  // edge_index row 1 (int32)
    const float* W1l = (const float*)d_in[2];
    const float* b1  = (const float*)d_in[3];
    const float* W1r = (const float*)d_in[4];
    const float* W2l = (const float*)d_in[5];
    const float* b2  = (const float*)d_in[6];
    const float* W2r = (const float*)d_in[7];
    float* out = (float*)d_out;

    // Lazy one-time stream/event creation (first call is the uncaptured
    // correctness run; nothing non-capturable happens during capture).
    static cudaStream_t s2 = nullptr;
    static cudaEvent_t evFork = nullptr, evB = nullptr, e1 = nullptr, e2 = nullptr, e3 = nullptr;
    static bool attrs_set = false;
    if (s2 == nullptr) {
        cudaStreamCreateWithFlags(&s2, cudaStreamNonBlocking);
        cudaEventCreateWithFlags(&evFork, cudaEventDisableTiming);
        cudaEventCreateWithFlags(&evB, cudaEventDisableTiming);
        cudaEventCreateWithFlags(&e1, cudaEventDisableTiming);
        cudaEventCreateWithFlags(&e2, cudaEventDisableTiming);
        cudaEventCreateWithFlags(&e3, cudaEventDisableTiming);
    }

    const int smem1 = (2 * 256 * 68 + 2 * 32 * 68) * 4;   // 156672 B
    const int smem2 = (2 * 128 * 68 + 2 * 64 * 68) * 4;   // 104448 B
    if (!attrs_set) {
        cudaFuncSetAttribute(k_gemmtc<256>, cudaFuncAttributeMaxDynamicSharedMemorySize, smem1);
        cudaFuncSetAttribute(k_gemmtc<128>, cudaFuncAttributeMaxDynamicSharedMemorySize, smem2);
        attrs_set = true;
    }

    const int egrid = (N_EDGES + 255) / 256;
    const int cgrid = (N_NODES * 32 + 255) / 256;

    // layer-2 tile split: 625 tiles of 64 rows; chunk A = [0,313) -> nodes [0,20032)
    const int T2      = (N_NODES + 63) / 64;   // 625
    const int T2_HALF = 313;
    const int NSPLIT  = T2_HALF * 64;          // 20032
    const int a1grid_A = ((NSPLIT) * 32 + 255) / 256;
    const int a1grid_B = ((N_NODES - NSPLIT) * 32 + 255) / 256;
    const int agrid    = (N_NODES * 32 + 255) / 256;

    cudaStream_t s0 = (cudaStream_t)0;

    // ---- fork: side chain = conv -> gemm1 (independent of CSR build) ----
    cudaEventRecord(evFork, s0);
    cudaStreamWaitEvent(s2, evFork, 0);
    k_conv<<<cgrid, 256, 0, s2>>>((const float4*)x);
    k_gemmtc<256><<<148, 256, smem1, s2>>>(W1l, W1r, 0, 1, 0, 1250);
    cudaEventRecord(evB, s2);

    // ---- main chain: CSR build ----
    k_dzero<<<(N_NODES + 255) / 256, 256, 0, s0>>>();
    k_hist<<<egrid, 256, 0, s0>>>(dst);
    k_scan<<<1, 1024, 0, s0>>>();
    k_permute<<<egrid, 256, 0, s0>>>(src, dst);

    // ---- join, then pipelined tail: agg1_A | (gemm2_A ∥ agg1_B) | gemm2_B ----
    cudaStreamWaitEvent(s0, evB, 0);
    k_agg1<<<a1grid_A, 256, 0, s0>>>(b1, 0, NSPLIT);
    cudaEventRecord(e1, s0);
    k_agg1<<<a1grid_B, 256, 0, s0>>>(b1, NSPLIT, N_NODES);
    cudaEventRecord(e2, s0);

    cudaStreamWaitEvent(s2, e1, 0);
    k_gemmtc<128><<<148, 256, smem2, s2>>>(W2l, W2r, 1, 2, 0, T2_HALF);
    cudaStreamWaitEvent(s2, e2, 0);
    k_gemmtc<128><<<148, 256, smem2, s2>>>(W2l, W2r, 1, 2, T2_HALF, T2);
    cudaEventRecord(e3, s2);

    // ---- final: aggregate + bias + log_softmax ----
    cudaStreamWaitEvent(s0, e3, 0);
    k_agg2<<<agrid, 256, 0, s0>>>(b2, out);

    (void)in_sizes; (void)n_in; (void)out_size;
}

// round 16
// speedup vs baseline: 1.1069x; 1.1069x over previous
#include <cuda_runtime.h>
#include <cuda_bf16.h>
#include <math.h>
#include <stdint.h>

#define N_NODES 40000
#define FEAT    128
#define HID     128
#define EMB     64
#define N_EDGES 640000

// Scratch: device globals, referenced ONLY from device code (host passes flags).
__device__ __align__(16) float    g_y1[N_NODES * 256];  // [t1|r1] per node (fp32)
__device__ __align__(16) float    g_y2[N_NODES * 128];  // [t2|r2] per node (fp32)
__device__ __align__(16) uint32_t g_xhi[N_NODES * 64];  // x as bf16x2 pairs (hi)
__device__ __align__(16) uint32_t g_xlo[N_NODES * 64];  // x residual (lo)
__device__ __align__(16) uint32_t g_hhi[N_NODES * 64];  // h as bf16x2 pairs (hi)
__device__ __align__(16) uint32_t g_hlo[N_NODES * 64];  // h residual (lo)
__device__ __align__(16) int g_deg[N_NODES];            // invariant: 0 at entry (restored by k_scan)
__device__ int g_rowptr[N_NODES + 1];
__device__ int g_woff[N_NODES];
__device__ int g_esrc[N_EDGES];

// ---------------------------------------------------------------------------
__device__ __forceinline__ void split2(float a, float b, uint32_t& h, uint32_t& l) {
    __nv_bfloat162 th, tl;
    th.x = __float2bfloat16_rn(a);
    th.y = __float2bfloat16_rn(b);
    tl.x = __float2bfloat16_rn(a - __bfloat162float(th.x));
    tl.y = __float2bfloat16_rn(b - __bfloat162float(th.y));
    h = reinterpret_cast<uint32_t&>(th);
    l = reinterpret_cast<uint32_t&>(tl);
}

__device__ __forceinline__ void mma_bf16(float d[4],
                                         uint32_t a0, uint32_t a1, uint32_t a2, uint32_t a3,
                                         uint32_t b0, uint32_t b1) {
    asm volatile(
        "mma.sync.aligned.m16n8k16.row.col.f32.bf16.bf16.f32 "
        "{%0,%1,%2,%3}, {%4,%5,%6,%7}, {%8,%9}, {%0,%1,%2,%3};\n"
        : "+f"(d[0]), "+f"(d[1]), "+f"(d[2]), "+f"(d[3])
        : "r"(a0), "r"(a1), "r"(a2), "r"(a3), "r"(b0), "r"(b1));
}

// ---------------------------------------------------------------------------
__global__ void k_hist(const int* __restrict__ dst) {
    int e = blockIdx.x * blockDim.x + threadIdx.x;
    if (e >= N_EDGES) return;
    int d = dst[e];
    if ((unsigned)d < N_NODES) atomicAdd(&g_deg[d], 1);
}

// single-block exclusive prefix scan of g_deg -> g_rowptr, g_woff.
// Also re-zeros g_deg (it is the last consumer), restoring the entry invariant
// so no separate zeroing kernel is needed.
__global__ __launch_bounds__(1024) void k_scan() {
    __shared__ int ssum[1024];
    const int t = threadIdx.x;
    const int CH = 40;                       // 1024*40 >= 40000
    int base = t * CH;
    int deg[CH];
    #pragma unroll
    for (int q = 0; q < CH / 4; q++) {
        int idx = base + q * 4;
        int4 v = (idx + 3 < N_NODES) ? ((const int4*)g_deg)[idx >> 2]
                                     : make_int4(idx + 0 < N_NODES ? g_deg[idx + 0] : 0,
                                                 idx + 1 < N_NODES ? g_deg[idx + 1] : 0,
                                                 idx + 2 < N_NODES ? g_deg[idx + 2] : 0,
                                                 idx + 3 < N_NODES ? g_deg[idx + 3] : 0);
        deg[q * 4 + 0] = v.x; deg[q * 4 + 1] = v.y;
        deg[q * 4 + 2] = v.z; deg[q * 4 + 3] = v.w;
    }
    int tsum = 0;
    #pragma unroll
    for (int c = 0; c < CH; c++) tsum += deg[c];
    ssum[t] = tsum;
    __syncthreads();
    for (int off = 1; off < 1024; off <<= 1) {
        int v = (t >= off) ? ssum[t - off] : 0;
        __syncthreads();
        ssum[t] += v;
        __syncthreads();
    }
    int running = ssum[t] - tsum;            // exclusive prefix
    #pragma unroll
    for (int c = 0; c < CH; c++) {
        int idx = base + c;
        if (idx < N_NODES) {
            g_rowptr[idx] = running;
            g_woff[idx]   = running;
            running += deg[c];
        }
    }
    if (t == 1023) g_rowptr[N_NODES] = running;
    // restore invariant: g_deg == 0 for the next call
    #pragma unroll
    for (int q = 0; q < CH / 4; q++) {
        int idx = base + q * 4;
        if (idx + 3 < N_NODES) {
            ((int4*)g_deg)[idx >> 2] = make_int4(0, 0, 0, 0);
        } else {
            for (int r = 0; r < 4; r++)
                if (idx + r < N_NODES) g_deg[idx + r] = 0;
        }
    }
}

__global__ void k_permute(const int* __restrict__ src, const int* __restrict__ dst) {
    int e = blockIdx.x * blockDim.x + threadIdx.x;
    if (e >= N_EDGES) return;
    int d = dst[e], s = src[e];
    if ((unsigned)d >= N_NODES || (unsigned)s >= N_NODES) return;
    int pos = atomicAdd(&g_woff[d], 1);
    g_esrc[pos] = s;
}

// ---------------------------------------------------------------------------
// split x into bf16 hi/lo pair arrays
__global__ void k_conv(const float4* __restrict__ x) {
    int i = blockIdx.x * blockDim.x + threadIdx.x;  // over N_NODES*32 float4s
    if (i >= N_NODES * 32) return;
    float4 v = x[i];
    uint32_t h0, l0, h1, l1;
    split2(v.x, v.y, h0, l0);
    split2(v.z, v.w, h1, l1);
    g_xhi[i * 2]     = h0;
    g_xhi[i * 2 + 1] = h1;
    g_xlo[i * 2]     = l0;
    g_xlo[i * 2 + 1] = l1;
}

// ---------------------------------------------------------------------------
// Tensor-core GEMM: y[n][0:N2] = x[n] . [Wl | Wr]^T  via bf16-split (3 products).
template<int N2>
__global__ __launch_bounds__(256)
void k_gemmtc(const float* __restrict__ Wl, const float* __restrict__ Wr,
              int use_gh, int y_sel) {
    constexpr int DOUT = N2 / 2;
    constexpr int WC   = N2 / 64;           // 4 (N2=256) or 2 (N2=128)
    constexpr int WR   = 8 / WC;            // 2 or 4
    constexpr int MBLK = 16 * WR;           // 32 or 64

    extern __shared__ uint32_t smu[];
    uint32_t* Bhi = smu;                    // N2*68
    uint32_t* Blo = Bhi + N2 * 68;
    uint32_t* Ahi = Blo + N2 * 68;          // MBLK*68
    uint32_t* Alo = Ahi + MBLK * 68;

    const uint32_t* xhi = use_gh ? g_hhi : g_xhi;
    const uint32_t* xlo = use_gh ? g_hlo : g_xlo;
    float* y = (y_sel == 1) ? g_y1 : g_y2;

    const int tid = threadIdx.x;

    for (int idx = tid; idx < DOUT * 64; idx += 256) {
        int j = idx >> 6, k2 = idx & 63;
        float2 wl = ((const float2*)Wl)[idx];
        float2 wr = ((const float2*)Wr)[idx];
        uint32_t h, l;
        split2(wl.x, wl.y, h, l);
        Bhi[j * 68 + k2] = h;  Blo[j * 68 + k2] = l;
        split2(wr.x, wr.y, h, l);
        Bhi[(DOUT + j) * 68 + k2] = h;  Blo[(DOUT + j) * 68 + k2] = l;
    }
    __syncthreads();

    const int w    = tid >> 5, lane = tid & 31;
    const int wrow = w % WR,   wcol = w / WR;
    const int mo   = wrow * 16, no  = wcol * 64;
    const int g    = lane >> 2, c   = lane & 3;
    const int ar0  = (mo + g) * 68, ar1 = (mo + g + 8) * 68;

    const int numTiles = N_NODES / MBLK;    // exact (1250 / 625)
    for (int tile = blockIdx.x; tile < numTiles; tile += gridDim.x) {
        int base = tile * MBLK;

        for (int idx = tid; idx < MBLK * 64; idx += 256) {
            int ln = idx >> 6, k2 = idx & 63;
            size_t gi = (size_t)(base + ln) * 64 + k2;
            Ahi[ln * 68 + k2] = xhi[gi];
            Alo[ln * 68 + k2] = xlo[gi];
        }
        __syncthreads();

        float d[8][4];
        #pragma unroll
        for (int nt = 0; nt < 8; nt++)
            #pragma unroll
            for (int q = 0; q < 4; q++) d[nt][q] = 0.f;

        #pragma unroll 2
        for (int ks = 0; ks < 8; ks++) {
            int kp = ks * 8 + c;
            uint32_t ah0 = Ahi[ar0 + kp],     ah1 = Ahi[ar1 + kp];
            uint32_t ah2 = Ahi[ar0 + kp + 4], ah3 = Ahi[ar1 + kp + 4];
            uint32_t al0 = Alo[ar0 + kp],     al1 = Alo[ar1 + kp];
            uint32_t al2 = Alo[ar0 + kp + 4], al3 = Alo[ar1 + kp + 4];
            #pragma unroll
            for (int nt = 0; nt < 8; nt++) {
                int nr = (no + nt * 8 + g) * 68 + kp;
                uint32_t bh0 = Bhi[nr], bh1 = Bhi[nr + 4];
                uint32_t bl0 = Blo[nr], bl1 = Blo[nr + 4];
                mma_bf16(d[nt], ah0, ah1, ah2, ah3, bh0, bh1);
                mma_bf16(d[nt], ah0, ah1, ah2, ah3, bl0, bl1);
                mma_bf16(d[nt], al0, al1, al2, al3, bh0, bh1);
            }
        }

        #pragma unroll
        for (int nt = 0; nt < 8; nt++) {
            int col = no + nt * 8 + 2 * c;
            size_t r0 = (size_t)(base + mo + g);
            *(float2*)(y + r0 * N2 + col)       = make_float2(d[nt][0], d[nt][1]);
            *(float2*)(y + (r0 + 8) * N2 + col) = make_float2(d[nt][2], d[nt][3]);
        }
        __syncthreads();
    }
}

// ---------------------------------------------------------------------------
// layer-1 aggregate+epilogue: h[n] = ELU( mean_j t1[src_j] + b1 + r1[n] )
__global__ void k_agg1(const float* __restrict__ b1) {
    int w    = (blockIdx.x * blockDim.x + threadIdx.x) >> 5;
    int lane = threadIdx.x & 31;
    if (w >= N_NODES) return;
    const float4* y4 = (const float4*)g_y1;   // row stride = 64 float4 ([t|r])
    int beg = g_rowptr[w], end = g_rowptr[w + 1];
    float4 acc = make_float4(0.f, 0.f, 0.f, 0.f);
    int i = beg;
    for (; i + 4 <= end; i += 4) {
        int s0 = g_esrc[i], s1 = g_esrc[i + 1], s2 = g_esrc[i + 2], s3 = g_esrc[i + 3];
        float4 v0 = y4[(size_t)s0 * 64 + lane];
        float4 v1 = y4[(size_t)s1 * 64 + lane];
        float4 v2 = y4[(size_t)s2 * 64 + lane];
        float4 v3 = y4[(size_t)s3 * 64 + lane];
        acc.x += v0.x + v1.x + v2.x + v3.x;
        acc.y += v0.y + v1.y + v2.y + v3.y;
        acc.z += v0.z + v1.z + v2.z + v3.z;
        acc.w += v0.w + v1.w + v2.w + v3.w;
    }
    for (; i < end; i++) {
        float4 v = y4[(size_t)g_esrc[i] * 64 + lane];
        acc.x += v.x; acc.y += v.y; acc.z += v.z; acc.w += v.w;
    }
    float rc = 1.0f / (float)max(end - beg, 1);
    float4 r = y4[(size_t)w * 64 + 32 + lane];
    float4 b = ((const float4*)b1)[lane];
    float4 o;
    o.x = acc.x * rc + b.x + r.x;
    o.y = acc.y * rc + b.y + r.y;
    o.z = acc.z * rc + b.z + r.z;
    o.w = acc.w * rc + b.w + r.w;
    o.x = (o.x > 0.f) ? o.x : expm1f(o.x);
    o.y = (o.y > 0.f) ? o.y : expm1f(o.y);
    o.z = (o.z > 0.f) ? o.z : expm1f(o.z);
    o.w = (o.w > 0.f) ? o.w : expm1f(o.w);
    uint32_t h0, l0, h1, l1;
    split2(o.x, o.y, h0, l0);
    split2(o.z, o.w, h1, l1);
    size_t pi = (size_t)w * 64 + lane * 2;
    g_hhi[pi]     = h0;  g_hhi[pi + 1] = h1;
    g_hlo[pi]     = l0;  g_hlo[pi + 1] = l1;
}

// ---------------------------------------------------------------------------
// layer-2 aggregate + bias + log_softmax
__global__ void k_agg2(const float* __restrict__ b2, float* __restrict__ out) {
    int w    = (blockIdx.x * blockDim.x + threadIdx.x) >> 5;
    int lane = threadIdx.x & 31;
    if (w >= N_NODES) return;
    const float2* y2 = (const float2*)g_y2;   // row stride = 64 float2 ([t|r])
    int beg = g_rowptr[w], end = g_rowptr[w + 1];
    float2 acc = make_float2(0.f, 0.f);
    int i = beg;
    for (; i + 4 <= end; i += 4) {
        int s0 = g_esrc[i], s1 = g_esrc[i + 1], s2 = g_esrc[i + 2], s3 = g_esrc[i + 3];
        float2 v0 = y2[(size_t)s0 * 64 + lane];
        float2 v1 = y2[(size_t)s1 * 64 + lane];
        float2 v2 = y2[(size_t)s2 * 64 + lane];
        float2 v3 = y2[(size_t)s3 * 64 + lane];
        acc.x += v0.x + v1.x + v2.x + v3.x;
        acc.y += v0.y + v1.y + v2.y + v3.y;
    }
    for (; i < end; i++) {
        float2 v = y2[(size_t)g_esrc[i] * 64 + lane];
        acc.x += v.x; acc.y += v.y;
    }
    float rc = 1.0f / (float)max(end - beg, 1);
    float2 r = y2[(size_t)w * 64 + 32 + lane];
    float2 b = ((const float2*)b2)[lane];
    float l0 = acc.x * rc + b.x + r.x;
    float l1 = acc.y * rc + b.y + r.y;
    float m = fmaxf(l0, l1);
    #pragma unroll
    for (int o = 16; o; o >>= 1) m = fmaxf(m, __shfl_xor_sync(0xFFFFFFFFu, m, o));
    float s = expf(l0 - m) + expf(l1 - m);
    #pragma unroll
    for (int o = 16; o; o >>= 1) s += __shfl_xor_sync(0xFFFFFFFFu, s, o);
    float lz = m + logf(s);
    ((float2*)out)[(size_t)w * 32 + lane] = make_float2(l0 - lz, l1 - lz);
}

// ---------------------------------------------------------------------------
extern "C" void kernel_launch(void* const* d_in, const int* in_sizes, int n_in,
                              void* d_out, int out_size) {
    const float* x   = (const float*)d_in[0];
    const int*   src = (const int*)d_in[1];            // edge_index row 0 (int32)
    const int*   dst = src + N_EDGES;                  // edge_index row 1 (int32)
    const float* W1l = (const float*)d_in[2];
    const float* b1  = (const float*)d_in[3];
    const float* W1r = (const float*)d_in[4];
    const float* W2l = (const float*)d_in[5];
    const float* b2  = (const float*)d_in[6];
    const float* W2r = (const float*)d_in[7];
    float* out = (float*)d_out;

    // Lazy one-time stream/event creation: first call is the (uncaptured)
    // correctness run, so none of this happens during graph capture.
    static cudaStream_t s2 = nullptr;
    static cudaEvent_t evFork = nullptr, evB = nullptr;
    static bool attrs_set = false;
    if (s2 == nullptr) {
        cudaStreamCreateWithFlags(&s2, cudaStreamNonBlocking);
        cudaEventCreateWithFlags(&evFork, cudaEventDisableTiming);
        cudaEventCreateWithFlags(&evB, cudaEventDisableTiming);
    }

    const int smem1 = (2 * 256 * 68 + 2 * 32 * 68) * 4;   // 156672 B
    const int smem2 = (2 * 128 * 68 + 2 * 64 * 68) * 4;   // 104448 B
    if (!attrs_set) {
        cudaFuncSetAttribute(k_gemmtc<256>, cudaFuncAttributeMaxDynamicSharedMemorySize, smem1);
        cudaFuncSetAttribute(k_gemmtc<128>, cudaFuncAttributeMaxDynamicSharedMemorySize, smem2);
        attrs_set = true;
    }

    const int egrid = (N_EDGES + 255) / 256;
    const int agrid = (N_NODES * 32 + 255) / 256;      // one warp per node
    const int cgrid = (N_NODES * 32 + 255) / 256;      // float4 granularity

    cudaStream_t s0 = (cudaStream_t)0;                 // main (captured) stream

    // ---- fork: side chain B = conv -> gemm1 (independent of CSR build) ----
    cudaEventRecord(evFork, s0);
    cudaStreamWaitEvent(s2, evFork, 0);
    k_conv<<<cgrid, 256, 0, s2>>>((const float4*)x);
    k_gemmtc<256><<<148, 256, smem1, s2>>>(W1l, W1r, 0, 1);
    cudaEventRecord(evB, s2);

    // ---- main chain A: CSR build (g_deg arrives zeroed; k_scan re-zeros it) ----
    k_hist<<<egrid, 256, 0, s0>>>(dst);
    k_scan<<<1, 1024, 0, s0>>>();
    k_permute<<<egrid, 256, 0, s0>>>(src, dst);

    // ---- join: agg1 needs g_y1 (chain B) + CSR (chain A) ----
    cudaStreamWaitEvent(s0, evB, 0);
    k_agg1<<<agrid, 256, 0, s0>>>(b1);

    // ---- layer 2 (sequential tail) ----
    k_gemmtc<128><<<296, 256, smem2, s0>>>(W2l, W2r, 1, 2);
    k_agg2<<<agrid, 256, 0, s0>>>(b2, out);

    (void)in_sizes; (void)n_in; (void)out_size;
}

// round 17
// speedup vs baseline: 1.2800x; 1.1564x over previous
#include <cuda_runtime.h>
#include <cuda_bf16.h>
#include <math.h>
#include <stdint.h>

#define N_NODES 40000
#define FEAT    128
#define HID     128
#define EMB     64
#define N_EDGES 640000
#define NSCAN_BLK 157          // ceil(40000/256)

// Scratch: device globals, referenced ONLY from device code (host passes flags).
__device__ __align__(16) float    g_y1[N_NODES * 256];  // [t1|r1] per node (fp32)
__device__ __align__(16) float    g_y2[N_NODES * 128];  // [t2|r2] per node (fp32)
__device__ __align__(16) uint32_t g_xhi[N_NODES * 64];  // x as bf16x2 pairs (hi)
__device__ __align__(16) uint32_t g_xlo[N_NODES * 64];  // x residual (lo)
__device__ __align__(16) uint32_t g_hhi[N_NODES * 64];  // h as bf16x2 pairs (hi)
__device__ __align__(16) uint32_t g_hlo[N_NODES * 64];  // h residual (lo)
__device__ __align__(16) int g_deg[N_NODES];            // invariant: 0 at entry (restored by k_wscan)
__device__ int g_rowptr[N_NODES + 1];
__device__ int g_woff[N_NODES];
__device__ int g_esrc[N_EDGES];
__device__ int g_bsum[NSCAN_BLK + 3];
__device__ int g_boff[NSCAN_BLK + 3];

// ---------------------------------------------------------------------------
__device__ __forceinline__ void split2(float a, float b, uint32_t& h, uint32_t& l) {
    __nv_bfloat162 th, tl;
    th.x = __float2bfloat16_rn(a);
    th.y = __float2bfloat16_rn(b);
    tl.x = __float2bfloat16_rn(a - __bfloat162float(th.x));
    tl.y = __float2bfloat16_rn(b - __bfloat162float(th.y));
    h = reinterpret_cast<uint32_t&>(th);
    l = reinterpret_cast<uint32_t&>(tl);
}

__device__ __forceinline__ void mma_bf16(float d[4],
                                         uint32_t a0, uint32_t a1, uint32_t a2, uint32_t a3,
                                         uint32_t b0, uint32_t b1) {
    asm volatile(
        "mma.sync.aligned.m16n8k16.row.col.f32.bf16.bf16.f32 "
        "{%0,%1,%2,%3}, {%4,%5,%6,%7}, {%8,%9}, {%0,%1,%2,%3};\n"
        : "+f"(d[0]), "+f"(d[1]), "+f"(d[2]), "+f"(d[3])
        : "r"(a0), "r"(a1), "r"(a2), "r"(a3), "r"(b0), "r"(b1));
}

// ---------------------------------------------------------------------------
__global__ void k_hist(const int* __restrict__ dst) {
    int e = blockIdx.x * blockDim.x + threadIdx.x;
    if (e >= N_EDGES) return;
    int d = dst[e];
    if ((unsigned)d < N_NODES) atomicAdd(&g_deg[d], 1);
}

// ---- multi-block exclusive scan of g_deg, 3 phases ----
// phase 1: per-block sums (256 nodes per block)
__global__ void k_bsum() {
    __shared__ int sw[8];
    int t   = threadIdx.x;
    int idx = blockIdx.x * 256 + t;
    int v   = (idx < N_NODES) ? g_deg[idx] : 0;
    #pragma unroll
    for (int o = 16; o; o >>= 1) v += __shfl_xor_sync(0xFFFFFFFFu, v, o);
    if ((t & 31) == 0) sw[t >> 5] = v;
    __syncthreads();
    if (t == 0) {
        int s = 0;
        #pragma unroll
        for (int q = 0; q < 8; q++) s += sw[q];
        g_bsum[blockIdx.x] = s;
    }
}

// phase 2: scan the block sums (single tiny block)
__global__ void k_bscan() {
    __shared__ int s[256];
    int t = threadIdx.x;
    int v = (t < NSCAN_BLK) ? g_bsum[t] : 0;
    s[t] = v;
    __syncthreads();
    for (int off = 1; off < 256; off <<= 1) {
        int u = (t >= off) ? s[t - off] : 0;
        __syncthreads();
        s[t] += u;
        __syncthreads();
    }
    if (t < NSCAN_BLK) g_boff[t] = s[t] - v;   // exclusive block offset
    if (t == 255) g_rowptr[N_NODES] = s[255];  // grand total
}

// phase 3: block-local scan + offset; writes rowptr/woff, re-zeros g_deg
__global__ void k_wscan() {
    __shared__ int s[256];
    int t   = threadIdx.x;
    int idx = blockIdx.x * 256 + t;
    int v   = (idx < N_NODES) ? g_deg[idx] : 0;
    s[t] = v;
    __syncthreads();
    for (int off = 1; off < 256; off <<= 1) {
        int u = (t >= off) ? s[t - off] : 0;
        __syncthreads();
        s[t] += u;
        __syncthreads();
    }
    if (idx < N_NODES) {
        int excl = s[t] - v + g_boff[blockIdx.x];
        g_rowptr[idx] = excl;
        g_woff[idx]   = excl;
        g_deg[idx]    = 0;                     // restore entry invariant
    }
}

__global__ void k_permute(const int* __restrict__ src, const int* __restrict__ dst) {
    int e = blockIdx.x * blockDim.x + threadIdx.x;
    if (e >= N_EDGES) return;
    int d = dst[e], s = src[e];
    if ((unsigned)d >= N_NODES || (unsigned)s >= N_NODES) return;
    int pos = atomicAdd(&g_woff[d], 1);
    g_esrc[pos] = s;
}

// ---------------------------------------------------------------------------
// split x into bf16 hi/lo pair arrays
__global__ void k_conv(const float4* __restrict__ x) {
    int i = blockIdx.x * blockDim.x + threadIdx.x;  // over N_NODES*32 float4s
    if (i >= N_NODES * 32) return;
    float4 v = x[i];
    uint32_t h0, l0, h1, l1;
    split2(v.x, v.y, h0, l0);
    split2(v.z, v.w, h1, l1);
    g_xhi[i * 2]     = h0;
    g_xhi[i * 2 + 1] = h1;
    g_xlo[i * 2]     = l0;
    g_xlo[i * 2 + 1] = l1;
}

// ---------------------------------------------------------------------------
// Tensor-core GEMM: y[n][0:N2] = x[n] . [Wl | Wr]^T  via bf16-split (3 products).
template<int N2>
__global__ __launch_bounds__(256)
void k_gemmtc(const float* __restrict__ Wl, const float* __restrict__ Wr,
              int use_gh, int y_sel) {
    constexpr int DOUT = N2 / 2;
    constexpr int WC   = N2 / 64;           // 4 (N2=256) or 2 (N2=128)
    constexpr int WR   = 8 / WC;            // 2 or 4
    constexpr int MBLK = 16 * WR;           // 32 or 64

    extern __shared__ uint32_t smu[];
    uint32_t* Bhi = smu;                    // N2*68
    uint32_t* Blo = Bhi + N2 * 68;
    uint32_t* Ahi = Blo + N2 * 68;          // MBLK*68
    uint32_t* Alo = Ahi + MBLK * 68;

    const uint32_t* xhi = use_gh ? g_hhi : g_xhi;
    const uint32_t* xlo = use_gh ? g_hlo : g_xlo;
    float* y = (y_sel == 1) ? g_y1 : g_y2;

    const int tid = threadIdx.x;

    for (int idx = tid; idx < DOUT * 64; idx += 256) {
        int j = idx >> 6, k2 = idx & 63;
        float2 wl = ((const float2*)Wl)[idx];
        float2 wr = ((const float2*)Wr)[idx];
        uint32_t h, l;
        split2(wl.x, wl.y, h, l);
        Bhi[j * 68 + k2] = h;  Blo[j * 68 + k2] = l;
        split2(wr.x, wr.y, h, l);
        Bhi[(DOUT + j) * 68 + k2] = h;  Blo[(DOUT + j) * 68 + k2] = l;
    }
    __syncthreads();

    const int w    = tid >> 5, lane = tid & 31;
    const int wrow = w % WR,   wcol = w / WR;
    const int mo   = wrow * 16, no  = wcol * 64;
    const int g    = lane >> 2, c   = lane & 3;
    const int ar0  = (mo + g) * 68, ar1 = (mo + g + 8) * 68;

    const int numTiles = N_NODES / MBLK;    // exact (1250 / 625)
    for (int tile = blockIdx.x; tile < numTiles; tile += gridDim.x) {
        int base = tile * MBLK;

        for (int idx = tid; idx < MBLK * 64; idx += 256) {
            int ln = idx >> 6, k2 = idx & 63;
            size_t gi = (size_t)(base + ln) * 64 + k2;
            Ahi[ln * 68 + k2] = xhi[gi];
            Alo[ln * 68 + k2] = xlo[gi];
        }
        __syncthreads();

        float d[8][4];
        #pragma unroll
        for (int nt = 0; nt < 8; nt++)
            #pragma unroll
            for (int q = 0; q < 4; q++) d[nt][q] = 0.f;

        #pragma unroll 2
        for (int ks = 0; ks < 8; ks++) {
            int kp = ks * 8 + c;
            uint32_t ah0 = Ahi[ar0 + kp],     ah1 = Ahi[ar1 + kp];
            uint32_t ah2 = Ahi[ar0 + kp + 4], ah3 = Ahi[ar1 + kp + 4];
            uint32_t al0 = Alo[ar0 + kp],     al1 = Alo[ar1 + kp];
            uint32_t al2 = Alo[ar0 + kp + 4], al3 = Alo[ar1 + kp + 4];
            #pragma unroll
            for (int nt = 0; nt < 8; nt++) {
                int nr = (no + nt * 8 + g) * 68 + kp;
                uint32_t bh0 = Bhi[nr], bh1 = Bhi[nr + 4];
                uint32_t bl0 = Blo[nr], bl1 = Blo[nr + 4];
                mma_bf16(d[nt], ah0, ah1, ah2, ah3, bh0, bh1);
                mma_bf16(d[nt], ah0, ah1, ah2, ah3, bl0, bl1);
                mma_bf16(d[nt], al0, al1, al2, al3, bh0, bh1);
            }
        }

        #pragma unroll
        for (int nt = 0; nt < 8; nt++) {
            int col = no + nt * 8 + 2 * c;
            size_t r0 = (size_t)(base + mo + g);
            *(float2*)(y + r0 * N2 + col)       = make_float2(d[nt][0], d[nt][1]);
            *(float2*)(y + (r0 + 8) * N2 + col) = make_float2(d[nt][2], d[nt][3]);
        }
        __syncthreads();
    }
}

// ---------------------------------------------------------------------------
// layer-1 aggregate+epilogue: h[n] = ELU( mean_j t1[src_j] + b1 + r1[n] )
__global__ void k_agg1(const float* __restrict__ b1) {
    int w    = (blockIdx.x * blockDim.x + threadIdx.x) >> 5;
    int lane = threadIdx.x & 31;
    if (w >= N_NODES) return;
    const float4* y4 = (const float4*)g_y1;   // row stride = 64 float4 ([t|r])
    int beg = g_rowptr[w], end = g_rowptr[w + 1];
    float4 acc = make_float4(0.f, 0.f, 0.f, 0.f);
    int i = beg;
    for (; i + 4 <= end; i += 4) {
        int s0 = g_esrc[i], s1 = g_esrc[i + 1], s2 = g_esrc[i + 2], s3 = g_esrc[i + 3];
        float4 v0 = y4[(size_t)s0 * 64 + lane];
        float4 v1 = y4[(size_t)s1 * 64 + lane];
        float4 v2 = y4[(size_t)s2 * 64 + lane];
        float4 v3 = y4[(size_t)s3 * 64 + lane];
        acc.x += v0.x + v1.x + v2.x + v3.x;
        acc.y += v0.y + v1.y + v2.y + v3.y;
        acc.z += v0.z + v1.z + v2.z + v3.z;
        acc.w += v0.w + v1.w + v2.w + v3.w;
    }
    for (; i < end; i++) {
        float4 v = y4[(size_t)g_esrc[i] * 64 + lane];
        acc.x += v.x; acc.y += v.y; acc.z += v.z; acc.w += v.w;
    }
    float rc = 1.0f / (float)max(end - beg, 1);
    float4 r = y4[(size_t)w * 64 + 32 + lane];
    float4 b = ((const float4*)b1)[lane];
    float4 o;
    o.x = acc.x * rc + b.x + r.x;
    o.y = acc.y * rc + b.y + r.y;
    o.z = acc.z * rc + b.z + r.z;
    o.w = acc.w * rc + b.w + r.w;
    o.x = (o.x > 0.f) ? o.x : expm1f(o.x);
    o.y = (o.y > 0.f) ? o.y : expm1f(o.y);
    o.z = (o.z > 0.f) ? o.z : expm1f(o.z);
    o.w = (o.w > 0.f) ? o.w : expm1f(o.w);
    uint32_t h0, l0, h1, l1;
    split2(o.x, o.y, h0, l0);
    split2(o.z, o.w, h1, l1);
    size_t pi = (size_t)w * 64 + lane * 2;
    g_hhi[pi]     = h0;  g_hhi[pi + 1] = h1;
    g_hlo[pi]     = l0;  g_hlo[pi + 1] = l1;
}

// ---------------------------------------------------------------------------
// layer-2 aggregate + bias + log_softmax
__global__ void k_agg2(const float* __restrict__ b2, float* __restrict__ out) {
    int w    = (blockIdx.x * blockDim.x + threadIdx.x) >> 5;
    int lane = threadIdx.x & 31;
    if (w >= N_NODES) return;
    const float2* y2 = (const float2*)g_y2;   // row stride = 64 float2 ([t|r])
    int beg = g_rowptr[w], end = g_rowptr[w + 1];
    float2 acc = make_float2(0.f, 0.f);
    int i = beg;
    for (; i + 4 <= end; i += 4) {
        int s0 = g_esrc[i], s1 = g_esrc[i + 1], s2 = g_esrc[i + 2], s3 = g_esrc[i + 3];
        float2 v0 = y2[(size_t)s0 * 64 + lane];
        float2 v1 = y2[(size_t)s1 * 64 + lane];
        float2 v2 = y2[(size_t)s2 * 64 + lane];
        float2 v3 = y2[(size_t)s3 * 64 + lane];
        acc.x += v0.x + v1.x + v2.x + v3.x;
        acc.y += v0.y + v1.y + v2.y + v3.y;
    }
    for (; i < end; i++) {
        float2 v = y2[(size_t)g_esrc[i] * 64 + lane];
        acc.x += v.x; acc.y += v.y;
    }
    float rc = 1.0f / (float)max(end - beg, 1);
    float2 r = y2[(size_t)w * 64 + 32 + lane];
    float2 b = ((const float2*)b2)[lane];
    float l0 = acc.x * rc + b.x + r.x;
    float l1 = acc.y * rc + b.y + r.y;
    float m = fmaxf(l0, l1);
    #pragma unroll
    for (int o = 16; o; o >>= 1) m = fmaxf(m, __shfl_xor_sync(0xFFFFFFFFu, m, o));
    float s = expf(l0 - m) + expf(l1 - m);
    #pragma unroll
    for (int o = 16; o; o >>= 1) s += __shfl_xor_sync(0xFFFFFFFFu, s, o);
    float lz = m + logf(s);
    ((float2*)out)[(size_t)w * 32 + lane] = make_float2(l0 - lz, l1 - lz);
}

// ---------------------------------------------------------------------------
extern "C" void kernel_launch(void* const* d_in, const int* in_sizes, int n_in,
                              void* d_out, int out_size) {
    const float* x   = (const float*)d_in[0];
    const int*   src = (const int*)d_in[1];            // edge_index row 0 (int32)
    const int*   dst = src + N_EDGES;                  // edge_index row 1 (int32)
    const float* W1l = (const float*)d_in[2];
    const float* b1  = (const float*)d_in[3];
    const float* W1r = (const float*)d_in[4];
    const float* W2l = (const float*)d_in[5];
    const float* b2  = (const float*)d_in[6];
    const float* W2r = (const float*)d_in[7];
    float* out = (float*)d_out;

    // Lazy one-time stream/event creation: first call is the (uncaptured)
    // correctness run, so none of this happens during graph capture.
    static cudaStream_t s2 = nullptr;
    static cudaEvent_t evFork = nullptr, evB = nullptr;
    static bool attrs_set = false;
    if (s2 == nullptr) {
        cudaStreamCreateWithFlags(&s2, cudaStreamNonBlocking);
        cudaEventCreateWithFlags(&evFork, cudaEventDisableTiming);
        cudaEventCreateWithFlags(&evB, cudaEventDisableTiming);
    }

    const int smem1 = (2 * 256 * 68 + 2 * 32 * 68) * 4;   // 156672 B
    const int smem2 = (2 * 128 * 68 + 2 * 64 * 68) * 4;   // 104448 B
    if (!attrs_set) {
        cudaFuncSetAttribute(k_gemmtc<256>, cudaFuncAttributeMaxDynamicSharedMemorySize, smem1);
        cudaFuncSetAttribute(k_gemmtc<128>, cudaFuncAttributeMaxDynamicSharedMemorySize, smem2);
        attrs_set = true;
    }

    const int egrid = (N_EDGES + 255) / 256;
    const int agrid = (N_NODES * 32 + 255) / 256;      // one warp per node
    const int cgrid = (N_NODES * 32 + 255) / 256;      // float4 granularity

    cudaStream_t s0 = (cudaStream_t)0;                 // main (captured) stream

    // ---- fork: side chain B = conv -> gemm1 (independent of CSR build) ----
    cudaEventRecord(evFork, s0);
    cudaStreamWaitEvent(s2, evFork, 0);
    k_conv<<<cgrid, 256, 0, s2>>>((const float4*)x);
    k_gemmtc<256><<<148, 256, smem1, s2>>>(W1l, W1r, 0, 1);
    cudaEventRecord(evB, s2);

    // ---- main chain A: CSR build (g_deg arrives zeroed; k_wscan re-zeros) ----
    k_hist<<<egrid, 256, 0, s0>>>(dst);
    k_bsum<<<NSCAN_BLK, 256, 0, s0>>>();
    k_bscan<<<1, 256, 0, s0>>>();
    k_wscan<<<NSCAN_BLK, 256, 0, s0>>>();
    k_permute<<<egrid, 256, 0, s0>>>(src, dst);

    // ---- join: agg1 needs g_y1 (chain B) + CSR (chain A) ----
    cudaStreamWaitEvent(s0, evB, 0);
    k_agg1<<<agrid, 256, 0, s0>>>(b1);

    // ---- layer 2 (sequential tail) ----
    k_gemmtc<128><<<296, 256, smem2, s0>>>(W2l, W2r, 1, 2);
    k_agg2<<<agrid, 256, 0, s0>>>(b2, out);

    (void)in_sizes; (void)n_in; (void)out_size;
}